// round 3
// baseline (speedup 1.0000x reference)
#include <cuda_runtime.h>
#include <math.h>
#include <stdint.h>

#define Bsz 256
#define Tt  512
#define Hh  512
#define Oo  128
#define MHh 512
#define Ff  256
#define NB  128
#define TPB 256

// ---------------- device scratch (statics; no cudaMalloc allowed) ----------
__device__ float g_WihI [Oo * 4 * Hh];      // gate-interleaved: [k][j*4+g]
__device__ float g_WhhI [Hh * 4 * Hh];
__device__ float g_bgI  [4 * Hh];
__device__ float g_Wf2hT[Ff * 2 * Hh];
__device__ float g_bhc  [2 * Hh];
__device__ float g_W12T [Hh * 2 * MHh];     // [k][p1|p2 hidden]
__device__ float g_b12  [2 * MHh];
__device__ float g_Wbd  [2 * MHh * 2 * Oo]; // block-diag [1024][256]
__device__ float g_b2cat[2 * Oo];
__device__ float g_offW1T[Hh * MHh];

__device__ float g_hb[2][Bsz * Hh];
__device__ float g_cb[2][Bsz * Hh];
__device__ float g_q [2][Bsz * 2 * MHh];    // PB K-split partials
__device__ float g_tmp[Bsz * 2 * Hh];
__device__ float g_hs [(size_t)Tt * Bsz * Hh];
__device__ float g_r0 [(size_t)Tt * Bsz * 2 * Oo];   // PC K-split partials (per t)
__device__ float g_r1 [(size_t)Tt * Bsz * 2 * Oo];
__device__ float g_hidOff[(size_t)Tt * Bsz * MHh];
__device__ int   g_nt[Tt];
__device__ unsigned g_barCount;

// ---------------- preprocessing ---------------------------------------------
__global__ void k_build_gates(const float* __restrict__ W_ih, const float* __restrict__ W_hh,
                              const float* __restrict__ b_ih, const float* __restrict__ b_hh) {
    int i = blockIdx.x * blockDim.x + threadIdx.x;
    if (i < Hh * 4 * Hh) {
        int k = i / 2048, n = i % 2048, j = n >> 2, g = n & 3;
        g_WhhI[i] = W_hh[(size_t)(g * Hh + j) * Hh + k];
    }
    if (i < Oo * 4 * Hh) {
        int k = i / 2048, n = i % 2048, j = n >> 2, g = n & 3;
        g_WihI[i] = W_ih[(size_t)(g * Hh + j) * Oo + k];
    }
    if (i < 4 * Hh) {
        int j = i >> 2, g = i & 3;
        g_bgI[i] = b_ih[g * Hh + j] + b_hh[g * Hh + j];
    }
}

__global__ void k_build_f2h(const float* __restrict__ W_f2h, const float* __restrict__ b_f2h) {
    int i = blockIdx.x * blockDim.x + threadIdx.x;
    if (i < Ff * 2 * Hh) {
        int k = i / (2 * Hh), j = i % (2 * Hh);
        int src_row = (j < Hh) ? 2 * j : 2 * (j - Hh) + 1;
        g_Wf2hT[i] = W_f2h[(size_t)src_row * Ff + k];
    }
    if (i < 2 * Hh) {
        int src_row = (i < Hh) ? 2 * i : 2 * (i - Hh) + 1;
        g_bhc[i] = b_f2h[src_row];
    }
}

__global__ void k_build_12(const float* __restrict__ p1_W1, const float* __restrict__ p2_W1,
                           const float* __restrict__ p1_b1, const float* __restrict__ p2_b1) {
    int i = blockIdx.x * blockDim.x + threadIdx.x;
    if (i < Hh * 2 * MHh) {
        int k = i / (2 * MHh), n = i % (2 * MHh);
        g_W12T[i] = (n < MHh) ? p1_W1[(size_t)n * Hh + k]
                              : p2_W1[(size_t)(n - MHh) * Hh + k];
    }
    if (i < 2 * MHh) g_b12[i] = (i < MHh) ? p1_b1[i] : p2_b1[i - MHh];
}

__global__ void k_build_bd(const float* __restrict__ p1_W2, const float* __restrict__ p2_W2,
                           const float* __restrict__ p1_b2, const float* __restrict__ p2_b2) {
    int i = blockIdx.x * blockDim.x + threadIdx.x;
    if (i < 2 * MHh * 2 * Oo) {
        int r = i / (2 * Oo), c = i % (2 * Oo);
        float v = 0.f;
        if (r < MHh && c < Oo)        v = p1_W2[(size_t)c * MHh + r];
        else if (r >= MHh && c >= Oo) v = p2_W2[(size_t)(c - Oo) * MHh + (r - MHh)];
        g_Wbd[i] = v;
    }
    if (i < 2 * Oo) g_b2cat[i] = (i < Oo) ? p1_b2[i] : p2_b2[i - Oo];
}

__global__ void k_transpose(float* dst, const float* __restrict__ src, int R, int C) {
    int i = blockIdx.x * blockDim.x + threadIdx.x;
    if (i >= R * C) return;
    int r = i / C, c = i % C;
    dst[(size_t)c * R + r] = src[i];
}

__global__ void k_misc(const int* __restrict__ lengths) {
    int i = blockIdx.x * blockDim.x + threadIdx.x;
    if (i == 0) g_barCount = 0u;
    if (i < Tt) {
        int c = 0;
        for (int b = 0; b < Bsz; ++b) c += (lengths[b] > i) ? 1 : 0;
        g_nt[i] = c;
    }
}

__global__ void k_split_hc() {
    int i = blockIdx.x * blockDim.x + threadIdx.x;
    if (i >= Bsz * Hh) return;
    int b = i >> 9, j = i & (Hh - 1);
    g_hb[0][i] = g_tmp[b * 1024 + j];
    g_cb[0][i] = g_tmp[b * 1024 + Hh + j];
}

// ---------------- generic 64x64 GEMM (init + offsets) -----------------------
template <int ACT>
__global__ void __launch_bounds__(256)
gemmG(const float* __restrict__ A, const float* __restrict__ Bm,
      const float* __restrict__ bias, float* __restrict__ C,
      int M, int N, int K, const int* __restrict__ aidx) {
    const int tid = threadIdx.x;
    const int tx = tid & 15, ty = tid >> 4;
    const int n0 = blockIdx.x * 64;
    const int m0 = blockIdx.y * 64;

    __shared__ __align__(16) float As[16][64];
    __shared__ __align__(16) float Bs[16][64];

    float acc[4][4];
#pragma unroll
    for (int i = 0; i < 4; ++i)
#pragma unroll
        for (int j = 0; j < 4; ++j) acc[i][j] = 0.f;

    for (int kt = 0; kt < K; kt += 16) {
#pragma unroll
        for (int i = 0; i < 4; ++i) {
            int mloc = ty + i * 16;
            int m = m0 + mloc;
            float v = 0.f;
            if (m < M) {
                int row = aidx ? aidx[m] : m;
                v = A[(size_t)row * K + kt + tx];
            }
            As[tx][mloc] = v;
        }
#pragma unroll
        for (int i = 0; i < 4; ++i) {
            int k = (tid >> 6) + i * 4;
            Bs[k][tid & 63] = Bm[(size_t)(kt + k) * N + n0 + (tid & 63)];
        }
        __syncthreads();
#pragma unroll
        for (int k = 0; k < 16; ++k) {
            float4 ra = *reinterpret_cast<const float4*>(&As[k][ty * 4]);
            float4 rb = *reinterpret_cast<const float4*>(&Bs[k][tx * 4]);
            float a[4] = {ra.x, ra.y, ra.z, ra.w};
            float b[4] = {rb.x, rb.y, rb.z, rb.w};
#pragma unroll
            for (int i = 0; i < 4; ++i)
#pragma unroll
                for (int j = 0; j < 4; ++j) acc[i][j] += a[i] * b[j];
        }
        __syncthreads();
    }

#pragma unroll
    for (int i = 0; i < 4; ++i) {
        int m = m0 + ty * 4 + i;
        if (m >= M) continue;
#pragma unroll
        for (int j = 0; j < 4; ++j) {
            int n = n0 + tx * 4 + j;
            float r = acc[i][j] + (bias ? bias[n] : 0.f);
            if (ACT == 1) r = tanhf(r);
            C[(size_t)m * N + n] = r;
        }
    }
}

// ---------------- persistent scan kernel -------------------------------------
__device__ __forceinline__ float sigm(float x) { return 1.f / (1.f + expf(-x)); }

__device__ __forceinline__ void gridsync(unsigned& phase) {
    __threadfence();
    __syncthreads();
    if (threadIdx.x == 0) {
        phase += 1u;
        const unsigned target = phase * NB;
        atomicAdd(&g_barCount, 1u);
        while (*((volatile unsigned*)&g_barCount) < target) {}
        __threadfence();   // invalidate L1 (gpu-scope fence -> CCTL.IVALL)
    }
    __syncthreads();
}

// 64x64 MAC with smem double-buffer via register prefetch.
// AF/BF are plain lambdas defined inside device code (no annotation needed).
template <class AF, class BF>
__device__ __forceinline__ void mac64(float (&acc)[4][4], int K, AF af, BF bf,
                                      float (*As)[64], float (*Bs)[64]) {
    const int tid = threadIdx.x;
    const int tx = tid & 15, ty = tid >> 4;
    const int bk = tid >> 6, bn = tid & 63;
    float ra[4], rb[4];
#pragma unroll
    for (int i = 0; i < 4; ++i) ra[i] = af(ty + i * 16, tx);
#pragma unroll
    for (int i = 0; i < 4; ++i) rb[i] = bf(bk + i * 4, bn);

    for (int kt = 0; kt < K; kt += 16) {
#pragma unroll
        for (int i = 0; i < 4; ++i) As[tx][ty + i * 16] = ra[i];
#pragma unroll
        for (int i = 0; i < 4; ++i) Bs[bk + i * 4][bn] = rb[i];
        __syncthreads();
        if (kt + 16 < K) {
#pragma unroll
            for (int i = 0; i < 4; ++i) ra[i] = af(ty + i * 16, kt + 16 + tx);
#pragma unroll
            for (int i = 0; i < 4; ++i) rb[i] = bf(kt + 16 + bk + i * 4, bn);
        }
#pragma unroll
        for (int k = 0; k < 16; ++k) {
            float4 a4 = *reinterpret_cast<const float4*>(&As[k][ty * 4]);
            float4 b4 = *reinterpret_cast<const float4*>(&Bs[k][tx * 4]);
            float av[4] = {a4.x, a4.y, a4.z, a4.w};
            float bv[4] = {b4.x, b4.y, b4.z, b4.w};
#pragma unroll
            for (int i = 0; i < 4; ++i)
#pragma unroll
                for (int j = 0; j < 4; ++j) acc[i][j] += av[i] * bv[j];
        }
        __syncthreads();
    }
}

__global__ void __launch_bounds__(TPB, 1) persistent_scan() {
    __shared__ __align__(16) float As[16][64];
    __shared__ __align__(16) float Bs[16][64];
    const int bid = blockIdx.x;
    const int tx = threadIdx.x & 15, ty = threadIdx.x >> 4;
    unsigned phase = 0;

    for (int t = 0; t < Tt; ++t) {
        const int nt = g_nt[t];
        const int mt = (nt + 63) >> 6;
        const int rd = t & 1, wr = rd ^ 1;
        const float* __restrict__ hR = g_hb[rd];
        float* __restrict__ hW = g_hb[wr];
        const float* __restrict__ cR = g_cb[rd];
        float* __restrict__ cW = g_cb[wr];

        // ---- PA: gates = x@WihI + h@WhhI, fused LSTM ----
        for (int tile = bid; tile < mt * 32; tile += NB) {
            const int m0 = (tile >> 5) << 6;
            const int n0 = (tile & 31) << 6;
            float acc[4][4];
#pragma unroll
            for (int i = 0; i < 4; ++i)
#pragma unroll
                for (int j = 0; j < 4; ++j) acc[i][j] = 0.f;

            if (t > 0) {
                const float* __restrict__ r0 = g_r0 + (size_t)(t - 1) * Bsz * 256;
                const float* __restrict__ r1 = g_r1 + (size_t)(t - 1) * Bsz * 256;
                mac64(acc, Oo,
                      [=] (int ml, int k) {
                          size_t idx = (size_t)(m0 + ml) * 256 + k;
                          return r0[idx] + r1[idx] + g_b2cat[k];
                      },
                      [=] (int k, int nl) { return g_WihI[k * 2048 + n0 + nl]; },
                      As, Bs);
            }
            mac64(acc, Hh,
                  [=] (int ml, int k) { return hR[(m0 + ml) * Hh + k]; },
                  [=] (int k, int nl) { return g_WhhI[(size_t)k * 2048 + n0 + nl]; },
                  As, Bs);

            const int jj = (n0 >> 2) + tx;
            float4 bg4 = *reinterpret_cast<const float4*>(&g_bgI[n0 + tx * 4]);
#pragma unroll
            for (int i = 0; i < 4; ++i) {
                int m = m0 + ty * 4 + i;
                if (m < nt) {
                    float gi = acc[i][0] + bg4.x;
                    float gf = acc[i][1] + bg4.y;
                    float gg = acc[i][2] + bg4.z;
                    float go = acc[i][3] + bg4.w;
                    float cn = sigm(gf) * cR[m * Hh + jj] + sigm(gi) * tanhf(gg);
                    float hn = sigm(go) * tanhf(cn);
                    cW[m * Hh + jj] = cn;
                    hW[m * Hh + jj] = hn;
                    g_hs[((size_t)t * Bsz + m) * Hh + jj] = hn;
                }
            }
        }
        gridsync(phase);

        // ---- PB: q[ks] = h @ W12T[ks*256:(ks+1)*256]  (K-split partials) ----
        for (int tile = bid; tile < mt * 32; tile += NB) {
            const int ks = tile & 1;
            const int n0 = ((tile >> 1) & 15) << 6;
            const int m0 = (tile >> 5) << 6;
            float* __restrict__ qout = g_q[ks];
            float acc[4][4];
#pragma unroll
            for (int i = 0; i < 4; ++i)
#pragma unroll
                for (int j = 0; j < 4; ++j) acc[i][j] = 0.f;
            mac64(acc, 256,
                  [=] (int ml, int k) { return hW[(m0 + ml) * Hh + ks * 256 + k]; },
                  [=] (int k, int nl) {
                      return g_W12T[(size_t)(ks * 256 + k) * 1024 + n0 + nl];
                  },
                  As, Bs);
#pragma unroll
            for (int i = 0; i < 4; ++i) {
                int m = m0 + ty * 4 + i;
#pragma unroll
                for (int j = 0; j < 4; ++j)
                    qout[(size_t)m * 1024 + n0 + tx * 4 + j] = acc[i][j];
            }
        }
        gridsync(phase);

        // ---- PC: r[ks] = tanh(q0+q1+b12) @ Wbd  (K-split partials, per t) ----
        for (int tile = bid; tile < mt * 8; tile += NB) {
            const int ks = tile & 1;
            const int n0 = ((tile >> 1) & 3) << 6;
            const int m0 = (tile >> 3) << 6;
            const int half = n0 >> 7;
            const int base = half * 512 + ks * 256;
            const float* __restrict__ q0 = g_q[0];
            const float* __restrict__ q1 = g_q[1];
            float* __restrict__ rout = (ks ? g_r1 : g_r0) + (size_t)t * Bsz * 256;
            float acc[4][4];
#pragma unroll
            for (int i = 0; i < 4; ++i)
#pragma unroll
                for (int j = 0; j < 4; ++j) acc[i][j] = 0.f;
            mac64(acc, 256,
                  [=] (int ml, int k) {
                      size_t idx = (size_t)(m0 + ml) * 1024 + base + k;
                      return tanhf(q0[idx] + q1[idx] + g_b12[base + k]);
                  },
                  [=] (int k, int nl) {
                      return g_Wbd[(size_t)(base + k) * 256 + n0 + nl];
                  },
                  As, Bs);
#pragma unroll
            for (int i = 0; i < 4; ++i) {
                int m = m0 + ty * 4 + i;
#pragma unroll
                for (int j = 0; j < 4; ++j)
                    rout[(size_t)m * 256 + n0 + tx * 4 + j] = acc[i][j];
            }
        }
        gridsync(phase);
    }
}

// ---------------- final stage -------------------------------------------------
__global__ void offsets_kernel(const float* __restrict__ offW2, const float* __restrict__ offb2,
                               float* __restrict__ out_off, int Np) {
    int warp = (blockIdx.x * blockDim.x + threadIdx.x) >> 5;
    int lane = threadIdx.x & 31;
    if (warp >= Np) return;
    const float* row = g_hidOff + (size_t)warp * MHh;
    float s = 0.f;
#pragma unroll
    for (int k = lane; k < MHh; k += 32) s += row[k] * offW2[k];
#pragma unroll
    for (int o = 16; o; o >>= 1) s += __shfl_xor_sync(0xFFFFFFFFu, s, o);
    if (lane == 0) out_off[warp] = s + offb2[0];
}

__global__ void gather_out(const int* __restrict__ pack_idx, float* __restrict__ out, int Np) {
    int gid = blockIdx.x * blockDim.x + threadIdx.x;
    if (gid >= Np * Oo) return;
    int i = gid >> 7, o = gid & 127;
    size_t p = (size_t)pack_idx[i];
    float v1 = g_r0[p * 256 + o] + g_r1[p * 256 + o] + g_b2cat[o];
    float v2 = g_r0[p * 256 + 128 + o] + g_r1[p * 256 + 128 + o] + g_b2cat[128 + o];
    size_t NO = (size_t)Np * Oo;
    out[(size_t)i * Oo + o] = v1;                 // flat_p1
    out[NO + (size_t)i * Oo + o] = v2;            // flat_p2
    out[2 * NO + Np + (size_t)i * Oo + o] = v1;   // flat_out (== flat_p1)
}

// ---------------- host ---------------------------------------------------------
static float* gsymf(const void* symbol) {
    void* p = nullptr;
    cudaGetSymbolAddress(&p, symbol);
    return (float*)p;
}

extern "C" void kernel_launch(void* const* d_in, const int* in_sizes, int n_in,
                              void* d_out, int out_size) {
    const float* features = (const float*)d_in[0];
    const float* W_f2h    = (const float*)d_in[1];
    const float* b_f2h    = (const float*)d_in[2];
    const float* W_ih     = (const float*)d_in[3];
    const float* W_hh     = (const float*)d_in[4];
    const float* b_ih     = (const float*)d_in[5];
    const float* b_hh     = (const float*)d_in[6];
    const float* p1_W1    = (const float*)d_in[7];
    const float* p1_b1    = (const float*)d_in[8];
    const float* p1_W2    = (const float*)d_in[9];
    const float* p1_b2    = (const float*)d_in[10];
    const float* p2_W1    = (const float*)d_in[11];
    const float* p2_b1    = (const float*)d_in[12];
    const float* p2_W2    = (const float*)d_in[13];
    const float* p2_b2    = (const float*)d_in[14];
    const float* off_W1   = (const float*)d_in[15];
    const float* off_b1   = (const float*)d_in[16];
    const float* off_W2   = (const float*)d_in[17];
    const float* off_b2   = (const float*)d_in[18];
    const int*   lengths  = (const int*)d_in[19];
    const int*   pack_idx = (const int*)d_in[20];
    float* out = (float*)d_out;
    const int Np = in_sizes[20];

    float* p_Wf2hT  = gsymf(g_Wf2hT);
    float* p_bhc    = gsymf(g_bhc);
    float* p_offW1T = gsymf(g_offW1T);
    float* p_tmp    = gsymf(g_tmp);
    float* p_hs     = gsymf(g_hs);
    float* p_hidOff = gsymf(g_hidOff);

    auto blocks = [](long long n) { return (unsigned)((n + 255) / 256); };

    // preprocessing
    k_build_gates<<<blocks(4LL * Hh * Hh), TPB>>>(W_ih, W_hh, b_ih, b_hh);
    k_build_f2h<<<blocks((long long)Ff * 2 * Hh), TPB>>>(W_f2h, b_f2h);
    k_build_12<<<blocks((long long)Hh * 2 * MHh), TPB>>>(p1_W1, p2_W1, p1_b1, p2_b1);
    k_build_bd<<<blocks(2LL * MHh * 2 * Oo), TPB>>>(p1_W2, p2_W2, p1_b2, p2_b2);
    k_transpose<<<blocks((long long)MHh * Hh), TPB>>>(p_offW1T, off_W1, MHh, Hh);
    k_misc<<<2, TPB>>>(lengths);

    // init: [h0|c0] = features @ Wf2hT + bhc, then split
    {
        dim3 grid((2 * Hh) / 64, Bsz / 64);
        gemmG<0><<<grid, TPB>>>(features, p_Wf2hT, p_bhc, p_tmp, Bsz, 2 * Hh, Ff, nullptr);
        k_split_hc<<<blocks(Bsz * Hh), TPB>>>();
    }

    // the whole scan in one persistent kernel (3 grid-syncs/step)
    persistent_scan<<<NB, TPB>>>();

    // offsets MLP over packed rows (gather fused into A load)
    {
        dim3 grid(MHh / 64, (unsigned)((Np + 63) / 64));
        gemmG<1><<<grid, TPB>>>(p_hs, p_offW1T, off_b1, p_hidOff, Np, MHh, Hh, pack_idx);
        offsets_kernel<<<(Np + 7) / 8, TPB>>>(off_W2, off_b2, out + 2 * (size_t)Np * Oo, Np);
    }

    // gather packed p1/p2/out (sums PC partials + bias)
    gather_out<<<blocks((long long)Np * Oo), TPB>>>(pack_idx, out, Np);
}

// round 5
// speedup vs baseline: 1.2235x; 1.2235x over previous
#include <cuda_runtime.h>
#include <math.h>
#include <stdint.h>

#define Bsz 256
#define Tt  512
#define Hh  512
#define Oo  128
#define MHh 512
#define Ff  256
#define NB  148
#define TPB 256
#define KSC 4   // PC K-split factor (fixed)

// ---------------- device scratch ----------------
__device__ float g_WihI [Oo * 4 * Hh];      // [k][j*4+g]
__device__ float g_WhhI [Hh * 4 * Hh];
__device__ float g_bgI  [4 * Hh];
__device__ float g_Wf2hT[Ff * 2 * Hh];
__device__ float g_bhc  [2 * Hh];
__device__ float g_W12T [Hh * 2 * MHh];     // [k][p1(0..511)|p2(512..1023)]
__device__ float g_b12  [2 * MHh];
__device__ float g_W2T1 [MHh * Oo];         // [k][n] = p1_W2[n][k]
__device__ float g_W2T2 [MHh * Oo];
__device__ float g_b2cat[2 * Oo];
__device__ float g_offW1T[Hh * MHh];

__device__ float g_hb[2][Bsz * Hh];
__device__ float g_cb[2][Bsz * Hh];
__device__ float g_gp[4][Bsz * 4 * Hh];              // PA partials (ks_a<=4)
__device__ float g_qp[8][Bsz * MHh];                 // PB partials (ks_b<=8), p1 half
__device__ float g_rp[KSC][(size_t)Tt * Bsz * Oo];   // PC partials per t
__device__ float g_hs [(size_t)Tt * Bsz * Hh];
__device__ float g_buf[(size_t)Tt * Bsz * MHh];      // offsets-hid, then reused for q2
__device__ int   g_nt[Tt];
__device__ unsigned g_barCount;

// ---------------- preprocessing (4 launches) ----------------
__global__ void k_build_gates(const float* __restrict__ W_ih, const float* __restrict__ W_hh,
                              const float* __restrict__ b_ih, const float* __restrict__ b_hh) {
    int i = blockIdx.x * blockDim.x + threadIdx.x;
    if (i < Hh * 4 * Hh) {
        int k = i / 2048, n = i % 2048, j = n >> 2, g = n & 3;
        g_WhhI[i] = W_hh[(size_t)(g * Hh + j) * Hh + k];
    }
    if (i < Oo * 4 * Hh) {
        int k = i / 2048, n = i % 2048, j = n >> 2, g = n & 3;
        g_WihI[i] = W_ih[(size_t)(g * Hh + j) * Oo + k];
    }
    if (i < 4 * Hh) {
        int j = i >> 2, g = i & 3;
        g_bgI[i] = b_ih[g * Hh + j] + b_hh[g * Hh + j];
    }
}

__global__ void k_build_f2h(const float* __restrict__ W_f2h, const float* __restrict__ b_f2h) {
    int i = blockIdx.x * blockDim.x + threadIdx.x;
    if (i < Ff * 2 * Hh) {
        int k = i / (2 * Hh), j = i % (2 * Hh);
        int src_row = (j < Hh) ? 2 * j : 2 * (j - Hh) + 1;
        g_Wf2hT[i] = W_f2h[(size_t)src_row * Ff + k];
    }
    if (i < 2 * Hh) {
        int src_row = (i < Hh) ? 2 * i : 2 * (i - Hh) + 1;
        g_bhc[i] = b_f2h[src_row];
    }
}

__global__ void k_build_12(const float* __restrict__ p1_W1, const float* __restrict__ p2_W1,
                           const float* __restrict__ p1_b1, const float* __restrict__ p2_b1,
                           const float* __restrict__ p1_W2, const float* __restrict__ p2_W2,
                           const float* __restrict__ p1_b2, const float* __restrict__ p2_b2) {
    int i = blockIdx.x * blockDim.x + threadIdx.x;
    if (i < Hh * 2 * MHh) {
        int k = i / (2 * MHh), n = i % (2 * MHh);
        g_W12T[i] = (n < MHh) ? p1_W1[(size_t)n * Hh + k]
                              : p2_W1[(size_t)(n - MHh) * Hh + k];
    }
    if (i < MHh * Oo) {
        int k = i >> 7, n = i & 127;
        g_W2T1[i] = p1_W2[(size_t)n * MHh + k];
        g_W2T2[i] = p2_W2[(size_t)n * MHh + k];
    }
    if (i < 2 * MHh) g_b12[i] = (i < MHh) ? p1_b1[i] : p2_b1[i - MHh];
    if (i < 2 * Oo)  g_b2cat[i] = (i < Oo) ? p1_b2[i] : p2_b2[i - Oo];
}

__global__ void k_build_misc(const float* __restrict__ off_W1, const int* __restrict__ lengths) {
    int i = blockIdx.x * blockDim.x + threadIdx.x;
    if (i < MHh * Hh) {
        int r = i / Hh, c = i % Hh;   // off_W1 [MH][H]
        g_offW1T[(size_t)c * MHh + r] = off_W1[i];
    }
    if (i == 0) g_barCount = 0u;
    if (i < Tt) {
        int c = 0;
        for (int b = 0; b < Bsz; ++b) c += (lengths[b] > i) ? 1 : 0;
        g_nt[i] = c;
    }
}

// ---------------- generic 64x64 GEMM (init + post-loop) ----------------
// MODE 0: C[m*N+n] = acc + bias
// MODE 1: tanh
// MODE 2: split h/c init: n<512 -> g_hb[0], else g_cb[0]
template <int MODE>
__global__ void __launch_bounds__(256)
gemmG(const float* __restrict__ A, const float* __restrict__ Bm, int ldb,
      const float* __restrict__ bias, float* __restrict__ C,
      int M, int N, int K, const int* __restrict__ aidx) {
    const int tid = threadIdx.x;
    const int tx = tid & 15, ty = tid >> 4;
    const int n0 = blockIdx.x * 64;
    const int m0 = blockIdx.y * 64;

    __shared__ __align__(16) float As[16][64];
    __shared__ __align__(16) float Bs[16][64];

    float acc[4][4];
#pragma unroll
    for (int i = 0; i < 4; ++i)
#pragma unroll
        for (int j = 0; j < 4; ++j) acc[i][j] = 0.f;

    for (int kt = 0; kt < K; kt += 16) {
#pragma unroll
        for (int i = 0; i < 4; ++i) {
            int mloc = ty + i * 16;
            int m = m0 + mloc;
            float v = 0.f;
            if (m < M) {
                int row = aidx ? aidx[m] : m;
                v = A[(size_t)row * K + kt + tx];
            }
            As[tx][mloc] = v;
        }
#pragma unroll
        for (int i = 0; i < 4; ++i) {
            int k = (tid >> 6) + i * 4;
            Bs[k][tid & 63] = Bm[(size_t)(kt + k) * ldb + n0 + (tid & 63)];
        }
        __syncthreads();
#pragma unroll
        for (int k = 0; k < 16; ++k) {
            float4 ra = *reinterpret_cast<const float4*>(&As[k][ty * 4]);
            float4 rb = *reinterpret_cast<const float4*>(&Bs[k][tx * 4]);
            float a[4] = {ra.x, ra.y, ra.z, ra.w};
            float b[4] = {rb.x, rb.y, rb.z, rb.w};
#pragma unroll
            for (int i = 0; i < 4; ++i)
#pragma unroll
                for (int j = 0; j < 4; ++j) acc[i][j] += a[i] * b[j];
        }
        __syncthreads();
    }

#pragma unroll
    for (int i = 0; i < 4; ++i) {
        int m = m0 + ty * 4 + i;
        if (m >= M) continue;
#pragma unroll
        for (int j = 0; j < 4; ++j) {
            int n = n0 + tx * 4 + j;
            float r = acc[i][j] + (bias ? bias[n] : 0.f);
            if (MODE == 1) r = tanhf(r);
            if (MODE == 2) {
                if (n < Hh) g_hb[0][m * Hh + n] = r;
                else        g_cb[0][m * Hh + (n - Hh)] = r;
            } else {
                C[(size_t)m * N + n] = r;
            }
        }
    }
}

// ---------------- persistent scan ----------------
__device__ __forceinline__ float sigm(float x) { return 1.f / (1.f + expf(-x)); }

__device__ __forceinline__ void gridsync(unsigned& phase) {
    __threadfence();
    __syncthreads();
    if (threadIdx.x == 0) {
        phase += 1u;
        const unsigned target = phase * NB;
        atomicAdd(&g_barCount, 1u);
        while (*((volatile unsigned*)&g_barCount) < target) {}
        __threadfence();
    }
    __syncthreads();
}

template <class AF, class BF>
__device__ __forceinline__ void mac64(float (&acc)[4][4], int K, AF af, BF bf,
                                      float (*As)[64], float (*Bs)[64]) {
    const int tid = threadIdx.x;
    const int tx = tid & 15, ty = tid >> 4;
    const int bk = tid >> 6, bn = tid & 63;
    float ra[4], rb[4];
#pragma unroll
    for (int i = 0; i < 4; ++i) ra[i] = af(ty + i * 16, tx);
#pragma unroll
    for (int i = 0; i < 4; ++i) rb[i] = bf(bk + i * 4, bn);

    for (int kt = 0; kt < K; kt += 16) {
#pragma unroll
        for (int i = 0; i < 4; ++i) As[tx][ty + i * 16] = ra[i];
#pragma unroll
        for (int i = 0; i < 4; ++i) Bs[bk + i * 4][bn] = rb[i];
        __syncthreads();
        if (kt + 16 < K) {
#pragma unroll
            for (int i = 0; i < 4; ++i) ra[i] = af(ty + i * 16, kt + 16 + tx);
#pragma unroll
            for (int i = 0; i < 4; ++i) rb[i] = bf(kt + 16 + bk + i * 4, bn);
        }
#pragma unroll
        for (int k = 0; k < 16; ++k) {
            float4 a4 = *reinterpret_cast<const float4*>(&As[k][ty * 4]);
            float4 b4 = *reinterpret_cast<const float4*>(&Bs[k][tx * 4]);
            float av[4] = {a4.x, a4.y, a4.z, a4.w};
            float bv[4] = {b4.x, b4.y, b4.z, b4.w};
#pragma unroll
            for (int i = 0; i < 4; ++i)
#pragma unroll
                for (int j = 0; j < 4; ++j) acc[i][j] += av[i] * bv[j];
        }
        __syncthreads();
    }
}

__global__ void __launch_bounds__(TPB, 1) persistent_scan() {
    __shared__ __align__(16) float As[16][64];
    __shared__ __align__(16) float Bs[16][64];
    const int bid = blockIdx.x;
    const int tid = threadIdx.x;
    const int tx = tid & 15, ty = tid >> 4;
    unsigned phase = 0;

    for (int t = 0; t < Tt; ++t) {
        const int nt = g_nt[t];
        const int mt = (nt + 63) >> 6;
        const int rd = t & 1, wr = rd ^ 1;
        const float* __restrict__ hR = g_hb[rd];
        float* __restrict__ hW = g_hb[wr];
        const float* __restrict__ cR = g_cb[rd];
        float* __restrict__ cW = g_cb[wr];
        const bool hasx = (t > 0);
        const int xoff = hasx ? 128 : 0;
        const int kspace = Hh + xoff;                 // 640 or 512
        const int ks_a = (mt >= 3) ? 1 : (mt == 2 ? 2 : 4);
        const int Ka = kspace / ks_a;
        const size_t rbase = hasx ? (size_t)(t - 1) * Bsz * Oo : 0;

        // ---- P0: gates partials (or fused LSTM when ks_a==1) ----
        const int tilesA = mt * 32 * ks_a;
        for (int tile = bid; tile < tilesA; tile += NB) {
            const int s  = tile % ks_a;
            const int u  = tile / ks_a;
            const int n0 = (u & 31) << 6;
            const int m0 = (u >> 5) << 6;
            const int k0 = s * Ka;
            float acc[4][4];
#pragma unroll
            for (int i = 0; i < 4; ++i)
#pragma unroll
                for (int j = 0; j < 4; ++j) acc[i][j] = 0.f;

            auto af = [&](int ml, int kk) {
                int gk = k0 + kk;
                int m = m0 + ml;
                if (hasx && gk < Oo) {
                    size_t ix = rbase + (size_t)m * Oo + gk;
                    float v = g_b2cat[gk];
#pragma unroll
                    for (int sc = 0; sc < KSC; ++sc) v += g_rp[sc][ix];
                    return v;
                }
                return hR[m * Hh + gk - xoff];
            };
            auto bf = [&](int kk, int nl) {
                int gk = k0 + kk;
                return (hasx && gk < Oo) ? g_WihI[gk * 2048 + n0 + nl]
                                         : g_WhhI[(size_t)(gk - xoff) * 2048 + n0 + nl];
            };
            mac64(acc, Ka, af, bf, As, Bs);

            if (ks_a == 1) {
                const int jj = (n0 >> 2) + tx;
                float4 bg4 = *reinterpret_cast<const float4*>(&g_bgI[n0 + tx * 4]);
#pragma unroll
                for (int i = 0; i < 4; ++i) {
                    int m = m0 + ty * 4 + i;
                    if (m < nt) {
                        float gi = acc[i][0] + bg4.x;
                        float gf = acc[i][1] + bg4.y;
                        float gg = acc[i][2] + bg4.z;
                        float go = acc[i][3] + bg4.w;
                        float cn = sigm(gf) * cR[m * Hh + jj] + sigm(gi) * tanhf(gg);
                        float hn = sigm(go) * tanhf(cn);
                        cW[m * Hh + jj] = cn;
                        hW[m * Hh + jj] = hn;
                        g_hs[((size_t)t * Bsz + m) * Hh + jj] = hn;
                    }
                }
            } else {
                float* __restrict__ gout = g_gp[s];
#pragma unroll
                for (int i = 0; i < 4; ++i) {
                    int m = m0 + ty * 4 + i;
#pragma unroll
                    for (int j = 0; j < 4; ++j)
                        gout[m * 2048 + n0 + tx * 4 + j] = acc[i][j];
                }
            }
        }
        gridsync(phase);

        // ---- P1: LSTM combine (only when PA was K-split) ----
        if (ks_a > 1) {
            const int total = mt * 64 * Hh;
            for (int e = bid * TPB + tid; e < total; e += NB * TPB) {
                int m = e >> 9, j = e & (Hh - 1);
                if (m < nt) {
                    float4 gs = make_float4(0.f, 0.f, 0.f, 0.f);
                    for (int s = 0; s < ks_a; ++s) {
                        float4 gp = *reinterpret_cast<const float4*>(&g_gp[s][m * 2048 + j * 4]);
                        gs.x += gp.x; gs.y += gp.y; gs.z += gp.z; gs.w += gp.w;
                    }
                    float4 bg = *reinterpret_cast<const float4*>(&g_bgI[j * 4]);
                    float cn = sigm(gs.y + bg.y) * cR[m * Hh + j] +
                               sigm(gs.x + bg.x) * tanhf(gs.z + bg.z);
                    float hn = sigm(gs.w + bg.w) * tanhf(cn);
                    cW[m * Hh + j] = cn;
                    hW[m * Hh + j] = hn;
                    g_hs[((size_t)t * Bsz + m) * Hh + j] = hn;
                }
            }
            gridsync(phase);
        }

        // ---- P2: q1 partials = h @ W12T[:, 0:512] ----
        const int ks_b = (mt <= 2) ? 8 : 4;
        const int Kb = MHh / ks_b;
        const int tilesB = mt * 8 * ks_b;
        for (int tile = bid; tile < tilesB; tile += NB) {
            const int s  = tile % ks_b;
            const int u  = tile / ks_b;
            const int n0 = (u & 7) << 6;
            const int m0 = (u >> 3) << 6;
            const int k0 = s * Kb;
            float* __restrict__ qout = g_qp[s];
            float acc[4][4];
#pragma unroll
            for (int i = 0; i < 4; ++i)
#pragma unroll
                for (int j = 0; j < 4; ++j) acc[i][j] = 0.f;
            auto af = [&](int ml, int kk) { return hW[(m0 + ml) * Hh + k0 + kk]; };
            auto bf = [&](int kk, int nl) {
                return g_W12T[(size_t)(k0 + kk) * 1024 + n0 + nl];
            };
            mac64(acc, Kb, af, bf, As, Bs);
#pragma unroll
            for (int i = 0; i < 4; ++i) {
                int m = m0 + ty * 4 + i;
#pragma unroll
                for (int j = 0; j < 4; ++j)
                    qout[m * MHh + n0 + tx * 4 + j] = acc[i][j];
            }
        }
        gridsync(phase);

        // ---- P3: p1 partials = tanh(sum q + b12) @ W2T1 ----
        const int Kc = MHh / KSC;    // 128
        const int tilesC = mt * 2 * KSC;
        for (int tile = bid; tile < tilesC; tile += NB) {
            const int s  = tile % KSC;
            const int u  = tile / KSC;
            const int n0 = (u & 1) << 6;
            const int m0 = (u >> 1) << 6;
            const int k0 = s * Kc;
            float* __restrict__ rout = g_rp[s] + (size_t)t * Bsz * Oo;
            float acc[4][4];
#pragma unroll
            for (int i = 0; i < 4; ++i)
#pragma unroll
                for (int j = 0; j < 4; ++j) acc[i][j] = 0.f;
            auto af = [&](int ml, int kk) {
                int k = k0 + kk;
                float v = g_b12[k];
                for (int s2 = 0; s2 < ks_b; ++s2) v += g_qp[s2][(m0 + ml) * MHh + k];
                return tanhf(v);
            };
            auto bf = [&](int kk, int nl) { return g_W2T1[(k0 + kk) * Oo + n0 + nl]; };
            mac64(acc, Kc, af, bf, As, Bs);
#pragma unroll
            for (int i = 0; i < 4; ++i) {
                int m = m0 + ty * 4 + i;
#pragma unroll
                for (int j = 0; j < 4; ++j)
                    rout[(size_t)m * Oo + n0 + tx * 4 + j] = acc[i][j];
            }
        }
        gridsync(phase);
    }
}

// ---------------- final stage ----------------
__global__ void offsets_kernel(const float* __restrict__ offW2, const float* __restrict__ offb2,
                               float* __restrict__ out_off, int Np) {
    int warp = (blockIdx.x * blockDim.x + threadIdx.x) >> 5;
    int lane = threadIdx.x & 31;
    if (warp >= Np) return;
    const float* row = g_buf + (size_t)warp * MHh;
    float s = 0.f;
#pragma unroll
    for (int k = lane; k < MHh; k += 32) s += row[k] * offW2[k];
#pragma unroll
    for (int o = 16; o; o >>= 1) s += __shfl_xor_sync(0xFFFFFFFFu, s, o);
    if (lane == 0) out_off[warp] = s + offb2[0];
}

__global__ void gather_out(const int* __restrict__ pack_idx, float* __restrict__ out, int Np) {
    int gid = blockIdx.x * blockDim.x + threadIdx.x;
    if (gid >= Np * Oo) return;
    int i = gid >> 7, o = gid & 127;
    size_t p = (size_t)pack_idx[i];
    float v1 = g_b2cat[o];
#pragma unroll
    for (int s = 0; s < KSC; ++s) v1 += g_rp[s][p * Oo + o];
    size_t NO = (size_t)Np * Oo;
    out[(size_t)i * Oo + o] = v1;                 // flat_p1
    out[2 * NO + Np + (size_t)i * Oo + o] = v1;   // flat_out (== flat_p1)
}

// ---------------- host ----------------
static float* gsymf(const void* symbol) {
    void* p = nullptr;
    cudaGetSymbolAddress(&p, symbol);
    return (float*)p;
}

extern "C" void kernel_launch(void* const* d_in, const int* in_sizes, int n_in,
                              void* d_out, int out_size) {
    const float* features = (const float*)d_in[0];
    const float* W_f2h    = (const float*)d_in[1];
    const float* b_f2h    = (const float*)d_in[2];
    const float* W_ih     = (const float*)d_in[3];
    const float* W_hh     = (const float*)d_in[4];
    const float* b_ih     = (const float*)d_in[5];
    const float* b_hh     = (const float*)d_in[6];
    const float* p1_W1    = (const float*)d_in[7];
    const float* p1_b1    = (const float*)d_in[8];
    const float* p1_W2    = (const float*)d_in[9];
    const float* p1_b2    = (const float*)d_in[10];
    const float* p2_W1    = (const float*)d_in[11];
    const float* p2_b1    = (const float*)d_in[12];
    const float* p2_W2    = (const float*)d_in[13];
    const float* p2_b2    = (const float*)d_in[14];
    const float* off_W1   = (const float*)d_in[15];
    const float* off_b1   = (const float*)d_in[16];
    const float* off_W2   = (const float*)d_in[17];
    const float* off_b2   = (const float*)d_in[18];
    const int*   lengths  = (const int*)d_in[19];
    const int*   pack_idx = (const int*)d_in[20];
    float* out = (float*)d_out;
    const int Np = in_sizes[20];
    const size_t NO = (size_t)Np * Oo;

    float* p_Wf2hT  = gsymf(g_Wf2hT);
    float* p_bhc    = gsymf(g_bhc);
    float* p_offW1T = gsymf(g_offW1T);
    float* p_W12T   = gsymf(g_W12T);
    float* p_b12    = gsymf(g_b12);
    float* p_W2T2   = gsymf(g_W2T2);
    float* p_b2cat  = gsymf(g_b2cat);
    float* p_hs     = gsymf(g_hs);
    float* p_buf    = gsymf(g_buf);

    auto blocks = [](long long n) { return (unsigned)((n + 255) / 256); };

    // prep (launches 1-4)
    k_build_gates<<<blocks(4LL * Hh * Hh), TPB>>>(W_ih, W_hh, b_ih, b_hh);
    k_build_f2h<<<blocks((long long)Ff * 2 * Hh), TPB>>>(W_f2h, b_f2h);
    k_build_12<<<blocks((long long)Hh * 2 * MHh), TPB>>>(p1_W1, p2_W1, p1_b1, p2_b1,
                                                         p1_W2, p2_W2, p1_b2, p2_b2);
    k_build_misc<<<blocks((long long)MHh * Hh), TPB>>>(off_W1, lengths);

    // init (launch 5): [h0|c0] = features @ Wf2hT + bhc, split in epilogue
    {
        dim3 grid((2 * Hh) / 64, Bsz / 64);
        gemmG<2><<<grid, TPB>>>(features, p_Wf2hT, 2 * Hh, p_bhc, nullptr,
                                Bsz, 2 * Hh, Ff, nullptr);
    }

    // the scan (launch 6 — ncu -s 5 -c 1 should capture this)
    persistent_scan<<<NB, TPB>>>();

    // post-loop: offsets MLP (packed gather fused into A load)
    {
        dim3 grid(MHh / 64, (unsigned)((Np + 63) / 64));
        gemmG<1><<<grid, TPB>>>(p_hs, p_offW1T, MHh, off_b1, p_buf,
                                Np, MHh, Hh, pack_idx);
        offsets_kernel<<<(Np + 7) / 8, TPB>>>(off_W2, off_b2, out + 2 * NO, Np);
    }

    // post-loop: p2 branch over packed rows (reuses g_buf after offsets done)
    {
        dim3 grid(MHh / 64, (unsigned)((Np + 63) / 64));
        gemmG<1><<<grid, TPB>>>(p_hs, p_W12T + MHh, 2 * MHh, p_b12 + MHh, p_buf,
                                Np, MHh, Hh, pack_idx);
        dim3 grid2(Oo / 64, (unsigned)((Np + 63) / 64));
        gemmG<0><<<grid2, TPB>>>(p_buf, p_W2T2, Oo, p_b2cat + Oo, out + NO,
                                 Np, Oo, MHh, nullptr);
    }

    // gather p1 / flat_out
    gather_out<<<blocks((long long)Np * Oo), TPB>>>(pack_idx, out, Np);
}

// round 6
// speedup vs baseline: 1.3057x; 1.0671x over previous
#include <cuda_runtime.h>
#include <math.h>
#include <stdint.h>

#define Bsz 256
#define Tt  512
#define Hh  512
#define Oo  128
#define MHh 512
#define Ff  256
#define NB  296
#define TPB 256
#define KSC 4   // PC K-split factor (fixed)

// ---------------- device scratch ----------------
__device__ float g_WihI [Oo * 4 * Hh];      // [k][j*4+g]
__device__ float g_WhhI [Hh * 4 * Hh];
__device__ float g_bgI  [4 * Hh];
__device__ float g_Wf2hT[Ff * 2 * Hh];
__device__ float g_bhc  [2 * Hh];
__device__ float g_W12T [Hh * 2 * MHh];     // [k][p1(0..511)|p2(512..1023)]
__device__ float g_b12  [2 * MHh];
__device__ float g_W2T1 [MHh * Oo];         // [k][n] = p1_W2[n][k]
__device__ float g_W2T2 [MHh * Oo];
__device__ float g_b2cat[2 * Oo];
__device__ float g_offW1T[Hh * MHh];

__device__ float g_hb[2][Bsz * Hh];
__device__ float g_cb[2][Bsz * Hh];
__device__ float g_gp[8][Bsz * 4 * Hh];              // PA partials (ks_a<=8)
__device__ float g_qp[8][Bsz * MHh];                 // PB partials (ks_b=8), p1 half
__device__ float g_rp[KSC][(size_t)Tt * Bsz * Oo];   // PC partials per t
__device__ float g_hs [(size_t)Tt * Bsz * Hh];
__device__ float g_buf[(size_t)Tt * Bsz * MHh];      // offsets-hid, then reused for q2
__device__ int   g_nt[Tt];
__device__ unsigned g_barCount;

// ---------------- preprocessing (4 launches) ----------------
__global__ void k_build_gates(const float* __restrict__ W_ih, const float* __restrict__ W_hh,
                              const float* __restrict__ b_ih, const float* __restrict__ b_hh) {
    int i = blockIdx.x * blockDim.x + threadIdx.x;
    if (i < Hh * 4 * Hh) {
        int k = i / 2048, n = i % 2048, j = n >> 2, g = n & 3;
        g_WhhI[i] = W_hh[(size_t)(g * Hh + j) * Hh + k];
    }
    if (i < Oo * 4 * Hh) {
        int k = i / 2048, n = i % 2048, j = n >> 2, g = n & 3;
        g_WihI[i] = W_ih[(size_t)(g * Hh + j) * Oo + k];
    }
    if (i < 4 * Hh) {
        int j = i >> 2, g = i & 3;
        g_bgI[i] = b_ih[g * Hh + j] + b_hh[g * Hh + j];
    }
}

__global__ void k_build_f2h(const float* __restrict__ W_f2h, const float* __restrict__ b_f2h) {
    int i = blockIdx.x * blockDim.x + threadIdx.x;
    if (i < Ff * 2 * Hh) {
        int k = i / (2 * Hh), j = i % (2 * Hh);
        int src_row = (j < Hh) ? 2 * j : 2 * (j - Hh) + 1;
        g_Wf2hT[i] = W_f2h[(size_t)src_row * Ff + k];
    }
    if (i < 2 * Hh) {
        int src_row = (i < Hh) ? 2 * i : 2 * (i - Hh) + 1;
        g_bhc[i] = b_f2h[src_row];
    }
}

__global__ void k_build_12(const float* __restrict__ p1_W1, const float* __restrict__ p2_W1,
                           const float* __restrict__ p1_b1, const float* __restrict__ p2_b1,
                           const float* __restrict__ p1_W2, const float* __restrict__ p2_W2,
                           const float* __restrict__ p1_b2, const float* __restrict__ p2_b2) {
    int i = blockIdx.x * blockDim.x + threadIdx.x;
    if (i < Hh * 2 * MHh) {
        int k = i / (2 * MHh), n = i % (2 * MHh);
        g_W12T[i] = (n < MHh) ? p1_W1[(size_t)n * Hh + k]
                              : p2_W1[(size_t)(n - MHh) * Hh + k];
    }
    if (i < MHh * Oo) {
        int k = i >> 7, n = i & 127;
        g_W2T1[i] = p1_W2[(size_t)n * MHh + k];
        g_W2T2[i] = p2_W2[(size_t)n * MHh + k];
    }
    if (i < 2 * MHh) g_b12[i] = (i < MHh) ? p1_b1[i] : p2_b1[i - MHh];
    if (i < 2 * Oo)  g_b2cat[i] = (i < Oo) ? p1_b2[i] : p2_b2[i - Oo];
}

__global__ void k_build_misc(const float* __restrict__ off_W1, const int* __restrict__ lengths) {
    int i = blockIdx.x * blockDim.x + threadIdx.x;
    if (i < MHh * Hh) {
        int r = i / Hh, c = i % Hh;   // off_W1 [MH][H]
        g_offW1T[(size_t)c * MHh + r] = off_W1[i];
    }
    if (i == 0) g_barCount = 0u;
    if (i < Tt) {
        int c = 0;
        for (int b = 0; b < Bsz; ++b) c += (lengths[b] > i) ? 1 : 0;
        g_nt[i] = c;
    }
}

// ---------------- generic 64x64 GEMM (init + post-loop) ----------------
// MODE 0: C[m*N+n] = acc + bias
// MODE 1: tanh
// MODE 2: split h/c init: n<512 -> g_hb[0], else g_cb[0]
template <int MODE>
__global__ void __launch_bounds__(256)
gemmG(const float* __restrict__ A, const float* __restrict__ Bm, int ldb,
      const float* __restrict__ bias, float* __restrict__ C,
      int M, int N, int K, const int* __restrict__ aidx) {
    const int tid = threadIdx.x;
    const int tx = tid & 15, ty = tid >> 4;
    const int n0 = blockIdx.x * 64;
    const int m0 = blockIdx.y * 64;

    __shared__ __align__(16) float As[16][64];
    __shared__ __align__(16) float Bs[16][64];

    float acc[4][4];
#pragma unroll
    for (int i = 0; i < 4; ++i)
#pragma unroll
        for (int j = 0; j < 4; ++j) acc[i][j] = 0.f;

    for (int kt = 0; kt < K; kt += 16) {
#pragma unroll
        for (int i = 0; i < 4; ++i) {
            int mloc = ty + i * 16;
            int m = m0 + mloc;
            float v = 0.f;
            if (m < M) {
                int row = aidx ? aidx[m] : m;
                v = A[(size_t)row * K + kt + tx];
            }
            As[tx][mloc] = v;
        }
#pragma unroll
        for (int i = 0; i < 4; ++i) {
            int k = (tid >> 6) + i * 4;
            Bs[k][tid & 63] = Bm[(size_t)(kt + k) * ldb + n0 + (tid & 63)];
        }
        __syncthreads();
#pragma unroll
        for (int k = 0; k < 16; ++k) {
            float4 ra = *reinterpret_cast<const float4*>(&As[k][ty * 4]);
            float4 rb = *reinterpret_cast<const float4*>(&Bs[k][tx * 4]);
            float a[4] = {ra.x, ra.y, ra.z, ra.w};
            float b[4] = {rb.x, rb.y, rb.z, rb.w};
#pragma unroll
            for (int i = 0; i < 4; ++i)
#pragma unroll
                for (int j = 0; j < 4; ++j) acc[i][j] += a[i] * b[j];
        }
        __syncthreads();
    }

#pragma unroll
    for (int i = 0; i < 4; ++i) {
        int m = m0 + ty * 4 + i;
        if (m >= M) continue;
#pragma unroll
        for (int j = 0; j < 4; ++j) {
            int n = n0 + tx * 4 + j;
            float r = acc[i][j] + (bias ? bias[n] : 0.f);
            if (MODE == 1) r = tanhf(r);
            if (MODE == 2) {
                if (n < Hh) g_hb[0][m * Hh + n] = r;
                else        g_cb[0][m * Hh + (n - Hh)] = r;
            } else {
                C[(size_t)m * N + n] = r;
            }
        }
    }
}

// ---------------- persistent scan ----------------
__device__ __forceinline__ float sigm(float x) { return 1.f / (1.f + expf(-x)); }

// CG-style grid barrier: fences only on thread 0 (bar.sync gives intra-CTA
// happens-before; t0's gpu-scope fence publishes the block's writes and the
// second fence + bar.sync makes remote writes visible to all threads).
__device__ __forceinline__ void gridsync(unsigned& phase) {
    __syncthreads();
    if (threadIdx.x == 0) {
        __threadfence();
        phase += 1u;
        const unsigned target = phase * NB;
        atomicAdd(&g_barCount, 1u);
        while (*((volatile unsigned*)&g_barCount) < target) { __nanosleep(64); }
        __threadfence();
    }
    __syncthreads();
}

template <class AF, class BF>
__device__ __forceinline__ void mac64(float (&acc)[4][4], int K, AF af, BF bf,
                                      float (*As)[64], float (*Bs)[64]) {
    const int tid = threadIdx.x;
    const int tx = tid & 15, ty = tid >> 4;
    const int bk = tid >> 6, bn = tid & 63;
    float ra[4], rb[4];
#pragma unroll
    for (int i = 0; i < 4; ++i) ra[i] = af(ty + i * 16, tx);
#pragma unroll
    for (int i = 0; i < 4; ++i) rb[i] = bf(bk + i * 4, bn);

    for (int kt = 0; kt < K; kt += 16) {
#pragma unroll
        for (int i = 0; i < 4; ++i) As[tx][ty + i * 16] = ra[i];
#pragma unroll
        for (int i = 0; i < 4; ++i) Bs[bk + i * 4][bn] = rb[i];
        __syncthreads();
        if (kt + 16 < K) {
#pragma unroll
            for (int i = 0; i < 4; ++i) ra[i] = af(ty + i * 16, kt + 16 + tx);
#pragma unroll
            for (int i = 0; i < 4; ++i) rb[i] = bf(kt + 16 + bk + i * 4, bn);
        }
#pragma unroll
        for (int k = 0; k < 16; ++k) {
            float4 a4 = *reinterpret_cast<const float4*>(&As[k][ty * 4]);
            float4 b4 = *reinterpret_cast<const float4*>(&Bs[k][tx * 4]);
            float av[4] = {a4.x, a4.y, a4.z, a4.w};
            float bv[4] = {b4.x, b4.y, b4.z, b4.w};
#pragma unroll
            for (int i = 0; i < 4; ++i)
#pragma unroll
                for (int j = 0; j < 4; ++j) acc[i][j] += av[i] * bv[j];
        }
        __syncthreads();
    }
}

__global__ void __launch_bounds__(TPB, 2) persistent_scan() {
    __shared__ __align__(16) float As[16][64];
    __shared__ __align__(16) float Bs[16][64];
    const int bid = blockIdx.x;
    const int tid = threadIdx.x;
    const int tx = tid & 15, ty = tid >> 4;
    unsigned phase = 0;

    for (int t = 0; t < Tt; ++t) {
        const int nt = g_nt[t];
        const int mt = (nt + 63) >> 6;
        const int rd = t & 1, wr = rd ^ 1;
        const float* __restrict__ hR = g_hb[rd];
        float* __restrict__ hW = g_hb[wr];
        const float* __restrict__ cR = g_cb[rd];
        float* __restrict__ cW = g_cb[wr];
        const bool hasx = (t > 0);
        const int xoff = hasx ? 128 : 0;
        const int kspace = Hh + xoff;                 // 640 or 512
        // keep tile count near NB: always K-split
        const int ks_a = (mt >= 3) ? 2 : (mt == 2 ? 4 : 8);
        const int Ka = kspace / ks_a;
        const size_t rbase = hasx ? (size_t)(t - 1) * Bsz * Oo : 0;

        // ---- P0: gates partials ----
        const int tilesA = mt * 32 * ks_a;
        for (int tile = bid; tile < tilesA; tile += NB) {
            const int s  = tile % ks_a;
            const int u  = tile / ks_a;
            const int n0 = (u & 31) << 6;
            const int m0 = (u >> 5) << 6;
            const int k0 = s * Ka;
            float acc[4][4];
#pragma unroll
            for (int i = 0; i < 4; ++i)
#pragma unroll
                for (int j = 0; j < 4; ++j) acc[i][j] = 0.f;

            auto af = [&](int ml, int kk) {
                int gk = k0 + kk;
                int m = m0 + ml;
                if (hasx && gk < Oo) {
                    size_t ix = rbase + (size_t)m * Oo + gk;
                    float v = g_b2cat[gk];
#pragma unroll
                    for (int sc = 0; sc < KSC; ++sc) v += g_rp[sc][ix];
                    return v;
                }
                return hR[m * Hh + gk - xoff];
            };
            auto bf = [&](int kk, int nl) {
                int gk = k0 + kk;
                return (hasx && gk < Oo) ? g_WihI[gk * 2048 + n0 + nl]
                                         : g_WhhI[(size_t)(gk - xoff) * 2048 + n0 + nl];
            };
            mac64(acc, Ka, af, bf, As, Bs);

            float* __restrict__ gout = g_gp[s];
#pragma unroll
            for (int i = 0; i < 4; ++i) {
                int m = m0 + ty * 4 + i;
#pragma unroll
                for (int j = 0; j < 4; ++j)
                    gout[m * 2048 + n0 + tx * 4 + j] = acc[i][j];
            }
        }
        gridsync(phase);

        // ---- P1: LSTM combine ----
        {
            const int total = mt * 64 * Hh;
            for (int e = bid * TPB + tid; e < total; e += NB * TPB) {
                int m = e >> 9, j = e & (Hh - 1);
                if (m < nt) {
                    float4 gs = make_float4(0.f, 0.f, 0.f, 0.f);
                    for (int s = 0; s < ks_a; ++s) {
                        float4 gp = *reinterpret_cast<const float4*>(&g_gp[s][m * 2048 + j * 4]);
                        gs.x += gp.x; gs.y += gp.y; gs.z += gp.z; gs.w += gp.w;
                    }
                    float4 bg = *reinterpret_cast<const float4*>(&g_bgI[j * 4]);
                    float cn = sigm(gs.y + bg.y) * cR[m * Hh + j] +
                               sigm(gs.x + bg.x) * tanhf(gs.z + bg.z);
                    float hn = sigm(gs.w + bg.w) * tanhf(cn);
                    cW[m * Hh + j] = cn;
                    hW[m * Hh + j] = hn;
                    g_hs[((size_t)t * Bsz + m) * Hh + j] = hn;
                }
            }
            gridsync(phase);
        }

        // ---- P2: q1 partials = h @ W12T[:, 0:512], K-split 8 ----
        const int ks_b = 8;
        const int Kb = MHh / ks_b;   // 64
        const int tilesB = mt * 8 * ks_b;
        for (int tile = bid; tile < tilesB; tile += NB) {
            const int s  = tile % ks_b;
            const int u  = tile / ks_b;
            const int n0 = (u & 7) << 6;
            const int m0 = (u >> 3) << 6;
            const int k0 = s * Kb;
            float* __restrict__ qout = g_qp[s];
            float acc[4][4];
#pragma unroll
            for (int i = 0; i < 4; ++i)
#pragma unroll
                for (int j = 0; j < 4; ++j) acc[i][j] = 0.f;
            auto af = [&](int ml, int kk) { return hW[(m0 + ml) * Hh + k0 + kk]; };
            auto bf = [&](int kk, int nl) {
                return g_W12T[(size_t)(k0 + kk) * 1024 + n0 + nl];
            };
            mac64(acc, Kb, af, bf, As, Bs);
#pragma unroll
            for (int i = 0; i < 4; ++i) {
                int m = m0 + ty * 4 + i;
#pragma unroll
                for (int j = 0; j < 4; ++j)
                    qout[m * MHh + n0 + tx * 4 + j] = acc[i][j];
            }
        }
        gridsync(phase);

        // ---- P3: p1 partials = tanh(sum q + b12) @ W2T1 ----
        const int Kc = MHh / KSC;    // 128
        const int tilesC = mt * 2 * KSC;
        for (int tile = bid; tile < tilesC; tile += NB) {
            const int s  = tile % KSC;
            const int u  = tile / KSC;
            const int n0 = (u & 1) << 6;
            const int m0 = (u >> 1) << 6;
            const int k0 = s * Kc;
            float* __restrict__ rout = g_rp[s] + (size_t)t * Bsz * Oo;
            float acc[4][4];
#pragma unroll
            for (int i = 0; i < 4; ++i)
#pragma unroll
                for (int j = 0; j < 4; ++j) acc[i][j] = 0.f;
            auto af = [&](int ml, int kk) {
                int k = k0 + kk;
                float v = g_b12[k];
#pragma unroll
                for (int s2 = 0; s2 < 8; ++s2) v += g_qp[s2][(m0 + ml) * MHh + k];
                return tanhf(v);
            };
            auto bf = [&](int kk, int nl) { return g_W2T1[(k0 + kk) * Oo + n0 + nl]; };
            mac64(acc, Kc, af, bf, As, Bs);
#pragma unroll
            for (int i = 0; i < 4; ++i) {
                int m = m0 + ty * 4 + i;
#pragma unroll
                for (int j = 0; j < 4; ++j)
                    rout[(size_t)m * Oo + n0 + tx * 4 + j] = acc[i][j];
            }
        }
        gridsync(phase);
    }
}

// ---------------- final stage ----------------
__global__ void offsets_kernel(const float* __restrict__ offW2, const float* __restrict__ offb2,
                               float* __restrict__ out_off, int Np) {
    int warp = (blockIdx.x * blockDim.x + threadIdx.x) >> 5;
    int lane = threadIdx.x & 31;
    if (warp >= Np) return;
    const float* row = g_buf + (size_t)warp * MHh;
    float s = 0.f;
#pragma unroll
    for (int k = lane; k < MHh; k += 32) s += row[k] * offW2[k];
#pragma unroll
    for (int o = 16; o; o >>= 1) s += __shfl_xor_sync(0xFFFFFFFFu, s, o);
    if (lane == 0) out_off[warp] = s + offb2[0];
}

__global__ void gather_out(const int* __restrict__ pack_idx, float* __restrict__ out, int Np) {
    int gid = blockIdx.x * blockDim.x + threadIdx.x;
    if (gid >= Np * Oo) return;
    int i = gid >> 7, o = gid & 127;
    size_t p = (size_t)pack_idx[i];
    float v1 = g_b2cat[o];
#pragma unroll
    for (int s = 0; s < KSC; ++s) v1 += g_rp[s][p * Oo + o];
    size_t NO = (size_t)Np * Oo;
    out[(size_t)i * Oo + o] = v1;                 // flat_p1
    out[2 * NO + Np + (size_t)i * Oo + o] = v1;   // flat_out (== flat_p1)
}

// ---------------- host ----------------
static float* gsymf(const void* symbol) {
    void* p = nullptr;
    cudaGetSymbolAddress(&p, symbol);
    return (float*)p;
}

extern "C" void kernel_launch(void* const* d_in, const int* in_sizes, int n_in,
                              void* d_out, int out_size) {
    const float* features = (const float*)d_in[0];
    const float* W_f2h    = (const float*)d_in[1];
    const float* b_f2h    = (const float*)d_in[2];
    const float* W_ih     = (const float*)d_in[3];
    const float* W_hh     = (const float*)d_in[4];
    const float* b_ih     = (const float*)d_in[5];
    const float* b_hh     = (const float*)d_in[6];
    const float* p1_W1    = (const float*)d_in[7];
    const float* p1_b1    = (const float*)d_in[8];
    const float* p1_W2    = (const float*)d_in[9];
    const float* p1_b2    = (const float*)d_in[10];
    const float* p2_W1    = (const float*)d_in[11];
    const float* p2_b1    = (const float*)d_in[12];
    const float* p2_W2    = (const float*)d_in[13];
    const float* p2_b2    = (const float*)d_in[14];
    const float* off_W1   = (const float*)d_in[15];
    const float* off_b1   = (const float*)d_in[16];
    const float* off_W2   = (const float*)d_in[17];
    const float* off_b2   = (const float*)d_in[18];
    const int*   lengths  = (const int*)d_in[19];
    const int*   pack_idx = (const int*)d_in[20];
    float* out = (float*)d_out;
    const int Np = in_sizes[20];
    const size_t NO = (size_t)Np * Oo;

    float* p_Wf2hT  = gsymf(g_Wf2hT);
    float* p_bhc    = gsymf(g_bhc);
    float* p_offW1T = gsymf(g_offW1T);
    float* p_W12T   = gsymf(g_W12T);
    float* p_b12    = gsymf(g_b12);
    float* p_W2T2   = gsymf(g_W2T2);
    float* p_b2cat  = gsymf(g_b2cat);
    float* p_hs     = gsymf(g_hs);
    float* p_buf    = gsymf(g_buf);

    auto blocks = [](long long n) { return (unsigned)((n + 255) / 256); };

    // prep (launches 1-4)
    k_build_gates<<<blocks(4LL * Hh * Hh), TPB>>>(W_ih, W_hh, b_ih, b_hh);
    k_build_f2h<<<blocks((long long)Ff * 2 * Hh), TPB>>>(W_f2h, b_f2h);
    k_build_12<<<blocks((long long)Hh * 2 * MHh), TPB>>>(p1_W1, p2_W1, p1_b1, p2_b1,
                                                         p1_W2, p2_W2, p1_b2, p2_b2);
    k_build_misc<<<blocks((long long)MHh * Hh), TPB>>>(off_W1, lengths);

    // init (launch 5): [h0|c0] = features @ Wf2hT + bhc, split in epilogue
    {
        dim3 grid((2 * Hh) / 64, Bsz / 64);
        gemmG<2><<<grid, TPB>>>(features, p_Wf2hT, 2 * Hh, p_bhc, nullptr,
                                Bsz, 2 * Hh, Ff, nullptr);
    }

    // the scan (launch 6)
    persistent_scan<<<NB, TPB>>>();

    // post-loop: offsets MLP (packed gather fused into A load)
    {
        dim3 grid(MHh / 64, (unsigned)((Np + 63) / 64));
        gemmG<1><<<grid, TPB>>>(p_hs, p_offW1T, MHh, off_b1, p_buf,
                                Np, MHh, Hh, pack_idx);
        offsets_kernel<<<(Np + 7) / 8, TPB>>>(off_W2, off_b2, out + 2 * NO, Np);
    }

    // post-loop: p2 branch over packed rows (reuses g_buf after offsets done)
    {
        dim3 grid(MHh / 64, (unsigned)((Np + 63) / 64));
        gemmG<1><<<grid, TPB>>>(p_hs, p_W12T + MHh, 2 * MHh, p_b12 + MHh, p_buf,
                                Np, MHh, Hh, pack_idx);
        dim3 grid2(Oo / 64, (unsigned)((Np + 63) / 64));
        gemmG<0><<<grid2, TPB>>>(p_buf, p_W2T2, Oo, p_b2cat + Oo, out + NO,
                                 Np, Oo, MHh, nullptr);
    }

    // gather p1 / flat_out
    gather_out<<<blocks((long long)Np * Oo), TPB>>>(pack_idx, out, Np);
}